// round 7
// baseline (speedup 1.0000x reference)
#include <cuda_runtime.h>
#include <cuda_bf16.h>

#define DEVI __device__ __forceinline__

constexpr int B_  = 4;
constexpr int H_  = 56;
constexpr int W_  = 56;
constexpr int C_  = 128;
constexpr int NH_ = 4;
constexpr int HD_ = 32;
constexpr int HW_ = H_ * W_;      // 3136
constexpr int M_  = B_ * HW_;     // 12544
constexpr float LOG2E  = 1.4426950408889634f;
constexpr float QSCALE = 0.17677669529663687f; // 32^-0.5

// scratch (no allocation allowed)
__device__ float g_qkv[3 * B_ * NH_ * HW_ * HD_];  // [which][b][head][pix][d]
__device__ float g_attn[M_ * C_];                  // [b*HW+pix][head*32+d]

// pack two f32 -> bf16x2 (x -> low half, y -> high half)
DEVI unsigned pk2(float x, float y) {
    unsigned u;
    asm("cvt.rn.bf16x2.f32 %0, %1, %2;" : "=r"(u) : "f"(y), "f"(x));
    return u;
}
DEVI void bsplit(float x, float &h, float &l) {
    __nv_bfloat16 b = __float2bfloat16(x);
    h = __bfloat162float(b);
    l = x - h;
}
DEVI void packhl(float x, float y, unsigned &ph, unsigned &pl) {
    float hx, lx, hy, ly;
    bsplit(x, hx, lx); bsplit(y, hy, ly);
    ph = pk2(hx, hy); pl = pk2(lx, ly);
}
DEVI void mma16(float* c, unsigned a0, unsigned a1, unsigned a2, unsigned a3,
                unsigned b0, unsigned b1) {
    asm("mma.sync.aligned.m16n8k16.row.col.f32.bf16.bf16.f32 "
        "{%0,%1,%2,%3},{%4,%5,%6,%7},{%8,%9},{%0,%1,%2,%3};"
        : "+f"(c[0]), "+f"(c[1]), "+f"(c[2]), "+f"(c[3])
        : "r"(a0), "r"(a1), "r"(a2), "r"(a3), "r"(b0), "r"(b1));
}

// ---------------------------------------------------------------------------
// bf16 3-term GEMM: C[M x N] = A[M x 128] * B[128 x N] + bias
// 512 threads = 16 warps (4m x 4n), block tile 128x128, warp tile 32x32,
// BK=16 (one k16 MMA chunk per stage), double-buffered smem, 1 sync/stage.
// smem packed bf16x2 over k-pairs; stride 136 (==8 mod 32): fragment LDS
// bank = 8*tg + g + const  -> permutation of 0..31, conflict-free.
// ---------------------------------------------------------------------------
template<int N, bool QKV>
__global__ void __launch_bounds__(512) gemm_bf(const float* __restrict__ A,
                                               const float* __restrict__ Bw,
                                               const float* __restrict__ bias,
                                               float* __restrict__ Cout)
{
    __shared__ unsigned Aph[2][8][136], Apl[2][8][136];
    __shared__ unsigned Bph[2][8][136], Bpl[2][8][136];

    const int tid  = threadIdx.x;
    const int lane = tid & 31;
    const int wid  = tid >> 5;
    const int g    = lane >> 2;
    const int tg   = lane & 3;
    const int wm   = wid & 3;      // m offset 32*wm
    const int wn   = wid >> 2;     // n offset 32*wn
    const int m0   = blockIdx.x * 128;
    const int n0   = blockIdx.y * 128;

    const float* Aeff = QKV ? A : (const float*)g_attn;

    // A loader: one float4 (4 consecutive k) per thread
    const int arow = tid & 127;
    const int kp0  = (tid >> 7) * 2;            // kp base (2 packed per thread)
    const float* Ap = Aeff + (size_t)(m0 + arow) * 128 + kp0 * 2;

    // B loader (tid<256): float4 along n, for k rows 2*bkp, 2*bkp+1
    const int bkp = (tid >> 5) & 7;
    const int bn4 = lane * 4;
    const float* Bp = Bw + n0 + bn4;

    float acc[2][4][4];
    #pragma unroll
    for (int i = 0; i < 2; i++)
        #pragma unroll
        for (int j = 0; j < 4; j++)
            #pragma unroll
            for (int e = 0; e < 4; e++) acc[i][j][e] = 0.0f;

    auto store_stage = [&](int buf, float4 a, float4 b0v, float4 b1v) {
        unsigned h0, l0, h1, l1;
        packhl(a.x, a.y, h0, l0);
        packhl(a.z, a.w, h1, l1);
        Aph[buf][kp0][arow]     = h0;  Apl[buf][kp0][arow]     = l0;
        Aph[buf][kp0 + 1][arow] = h1;  Apl[buf][kp0 + 1][arow] = l1;
        if (tid < 256) {
            float hA, lA, hB, lB;
            unsigned ph[4], pl[4];
            bsplit(b0v.x, hA, lA); bsplit(b1v.x, hB, lB); ph[0] = pk2(hA, hB); pl[0] = pk2(lA, lB);
            bsplit(b0v.y, hA, lA); bsplit(b1v.y, hB, lB); ph[1] = pk2(hA, hB); pl[1] = pk2(lA, lB);
            bsplit(b0v.z, hA, lA); bsplit(b1v.z, hB, lB); ph[2] = pk2(hA, hB); pl[2] = pk2(lA, lB);
            bsplit(b0v.w, hA, lA); bsplit(b1v.w, hB, lB); ph[3] = pk2(hA, hB); pl[3] = pk2(lA, lB);
            *(uint4*)&Bph[buf][bkp][bn4] = make_uint4(ph[0], ph[1], ph[2], ph[3]);
            *(uint4*)&Bpl[buf][bkp][bn4] = make_uint4(pl[0], pl[1], pl[2], pl[3]);
        }
    };

    auto compute = [&](int buf) {
        unsigned bh0[4], bh1[4], bl0[4], bl1[4];
        #pragma unroll
        for (int na = 0; na < 4; na++) {
            const int n = wn * 32 + na * 8 + g;
            bh0[na] = Bph[buf][tg][n];     bh1[na] = Bph[buf][tg + 4][n];
            bl0[na] = Bpl[buf][tg][n];     bl1[na] = Bpl[buf][tg + 4][n];
        }
        #pragma unroll
        for (int ma = 0; ma < 2; ma++) {
            const int m = wm * 32 + ma * 16 + g;
            unsigned ah0 = Aph[buf][tg][m],     ah1 = Aph[buf][tg][m + 8];
            unsigned ah2 = Aph[buf][tg + 4][m], ah3 = Aph[buf][tg + 4][m + 8];
            unsigned al0 = Apl[buf][tg][m],     al1 = Apl[buf][tg][m + 8];
            unsigned al2 = Apl[buf][tg + 4][m], al3 = Apl[buf][tg + 4][m + 8];
            #pragma unroll
            for (int na = 0; na < 4; na++)
                mma16(acc[ma][na], ah0, ah1, ah2, ah3, bh0[na], bh1[na]);
            #pragma unroll
            for (int na = 0; na < 4; na++)
                mma16(acc[ma][na], ah0, ah1, ah2, ah3, bl0[na], bl1[na]);
            #pragma unroll
            for (int na = 0; na < 4; na++)
                mma16(acc[ma][na], al0, al1, al2, al3, bh0[na], bh1[na]);
        }
    };

    float4 va = *(const float4*)Ap;
    float4 vb0 = make_float4(0, 0, 0, 0), vb1 = make_float4(0, 0, 0, 0);
    if (tid < 256) {
        vb0 = *(const float4*)(Bp + (size_t)(2 * bkp) * N);
        vb1 = *(const float4*)(Bp + (size_t)(2 * bkp + 1) * N);
    }
    store_stage(0, va, vb0, vb1);
    __syncthreads();

    #pragma unroll 1
    for (int s = 0; s < 8; s++) {
        float4 xa = make_float4(0, 0, 0, 0);
        float4 xb0 = make_float4(0, 0, 0, 0), xb1 = make_float4(0, 0, 0, 0);
        if (s < 7) {
            const int k0 = (s + 1) * 16;
            xa = *(const float4*)(Ap + k0);
            if (tid < 256) {
                xb0 = *(const float4*)(Bp + (size_t)(k0 + 2 * bkp) * N);
                xb1 = *(const float4*)(Bp + (size_t)(k0 + 2 * bkp + 1) * N);
            }
        }
        compute(s & 1);
        if (s < 7) { store_stage((s + 1) & 1, xa, xb0, xb1); __syncthreads(); }
    }

    // epilogue
    #pragma unroll
    for (int ma = 0; ma < 2; ma++) {
        #pragma unroll
        for (int half = 0; half < 2; half++) {
            const int m = m0 + wm * 32 + ma * 16 + g + half * 8;
            int bb = 0, pix = 0;
            if (QKV) { bb = m / HW_; pix = m - bb * HW_; }
            #pragma unroll
            for (int na = 0; na < 4; na++) {
                const int nl = wn * 32 + na * 8 + tg * 2;
                const float2 bv = *(const float2*)&bias[n0 + nl];
                float o0 = acc[ma][na][half * 2 + 0] + bv.x;
                float o1 = acc[ma][na][half * 2 + 1] + bv.y;
                if (QKV) {
                    const int which = n0 >> 7;        // 0=q,1=k,2=v
                    const int d = na * 8 + tg * 2;    // nl & 31 (head = wn)
                    if (which == 0) { o0 *= QSCALE * LOG2E; o1 *= QSCALE * LOG2E; }
                    float* dst = g_qkv +
                        ((size_t)((which * B_ + bb) * NH_ + wn) * HW_ + pix) * HD_ + d;
                    *(float2*)dst = make_float2(o0, o1);
                } else {
                    *(float2*)&Cout[(size_t)m * 128 + nl] = make_float2(o0, o1);
                }
            }
        }
    }
}

// ---------------------------------------------------------------------------
// Tensor-core neighborhood attention.
// CTA = 128 thr (4 warps) = 8x8 query tile for one (b, head).
// S[64 x 208] = Q * K^T over padded 14x14 key union (dense MMA, invalid cols
// masked at softmax), P kept IN REGISTERS in A-frag layout (accum cols tg*2
// == A-frag k cols), split hi/lo bf16 -> 3-pass P*V.
// K: Kp[dp=d/2][key], stride 232 (==8 mod 32) -> B-frag LDS conflict-free.
// V: Vp[kp=key/2][d] hi+lo, stride 40 (==8 mod 32) -> conflict-free.
// bias: idx = (ki0-qi+6)*13 + (kj0-qj+6) + r*13 + cc (affine in key coords).
// ---------------------------------------------------------------------------
constexpr int KSTR = 232;
constexpr int VSTR = 40;

DEVI float pexp(float s, int r, int cc, int r0q, int c0q, int cb,
                float &sum, const float* bs) {
    const bool v = ((unsigned)(r - r0q) < 7u) && ((unsigned)(cc - c0q) < 7u);
    const int idx = v ? (cb + r * 13 + cc) : 0;
    const float pr = v ? exp2f(s + bs[idx]) : 0.0f;
    sum += pr;
    return pr;
}

__global__ void __launch_bounds__(128) attn_tc(const float* __restrict__ rpb)
{
    __shared__ unsigned Kp[16][KSTR];      // 14848 B
    __shared__ unsigned Vph[104][VSTR];    // 16640 B
    __shared__ unsigned Vpl[104][VSTR];    // 16640 B
    __shared__ float bs[169];              //   676 B   (total 48804)

    const int b  = blockIdx.z;
    const int h  = blockIdx.y;
    const int i0 = (blockIdx.x / 7) * 8;
    const int j0 = (blockIdx.x % 7) * 8;
    const int ki0 = min(max(i0 - 3, 0), H_ - 7);
    const int kj0 = min(max(j0 - 3, 0), W_ - 7);
    const int tid = threadIdx.x, lane = tid & 31, w = tid >> 5;
    const int g = lane >> 2, tg = lane & 3;

    const float* qb = g_qkv + (size_t)((0 * B_ + b) * NH_ + h) * HW_ * HD_;
    const float* kb = g_qkv + (size_t)((1 * B_ + b) * NH_ + h) * HW_ * HD_;
    const float* vb = g_qkv + (size_t)((2 * B_ + b) * NH_ + h) * HW_ * HD_;

    for (int x = tid; x < 169; x += 128) bs[x] = rpb[h * 169 + x] * LOG2E;

    // ---- K pack (single bf16) ----
    for (int key = tid; key < 208; key += 128) {
        if (key < 196) {
            const int gi = ki0 + key / 14, gj = kj0 + key % 14;
            const float4* p = (const float4*)(kb + (size_t)(gi * W_ + gj) * HD_);
            #pragma unroll
            for (int t = 0; t < 8; t++) {
                const float4 v = p[t];
                Kp[2 * t][key]     = pk2(v.x, v.y);
                Kp[2 * t + 1][key] = pk2(v.z, v.w);
            }
        } else {
            #pragma unroll
            for (int dp = 0; dp < 16; dp++) Kp[dp][key] = 0u;
        }
    }

    // ---- V pack (hi/lo), pairs over key ----
    if (tid < 104) {
        const int kp = tid;
        const int k0 = 2 * kp, k1 = 2 * kp + 1;
        const float4* p0 = nullptr;
        const float4* p1 = nullptr;
        if (k0 < 196) { int gi = ki0 + k0 / 14, gj = kj0 + k0 % 14;
                        p0 = (const float4*)(vb + (size_t)(gi * W_ + gj) * HD_); }
        if (k1 < 196) { int gi = ki0 + k1 / 14, gj = kj0 + k1 % 14;
                        p1 = (const float4*)(vb + (size_t)(gi * W_ + gj) * HD_); }
        #pragma unroll
        for (int t = 0; t < 8; t++) {
            const float4 a = p0 ? p0[t] : make_float4(0, 0, 0, 0);
            const float4 c = p1 ? p1[t] : make_float4(0, 0, 0, 0);
            float ha, la, hb, lb;
            bsplit(a.x, ha, la); bsplit(c.x, hb, lb);
            Vph[kp][4 * t + 0] = pk2(ha, hb); Vpl[kp][4 * t + 0] = pk2(la, lb);
            bsplit(a.y, ha, la); bsplit(c.y, hb, lb);
            Vph[kp][4 * t + 1] = pk2(ha, hb); Vpl[kp][4 * t + 1] = pk2(la, lb);
            bsplit(a.z, ha, la); bsplit(c.z, hb, lb);
            Vph[kp][4 * t + 2] = pk2(ha, hb); Vpl[kp][4 * t + 2] = pk2(la, lb);
            bsplit(a.w, ha, la); bsplit(c.w, hb, lb);
            Vph[kp][4 * t + 3] = pk2(ha, hb); Vpl[kp][4 * t + 3] = pk2(la, lb);
        }
    }

    // ---- Q fragments (single bf16; q pre-scaled by QSCALE*LOG2E) ----
    const int ql0 = w * 16 + g, ql1 = ql0 + 8;
    const int qi0 = i0 + (ql0 >> 3), qj0 = j0 + (ql0 & 7);
    const int qi1 = i0 + (ql1 >> 3), qj1 = j0 + (ql1 & 7);
    const float* q0p = qb + (size_t)(qi0 * W_ + qj0) * HD_ + tg * 2;
    const float* q1p = qb + (size_t)(qi1 * W_ + qj1) * HD_ + tg * 2;
    unsigned aq[2][4];
    #pragma unroll
    for (int kc = 0; kc < 2; kc++) {
        float2 f;
        f = *(const float2*)(q0p + kc * 16);     aq[kc][0] = pk2(f.x, f.y);
        f = *(const float2*)(q1p + kc * 16);     aq[kc][1] = pk2(f.x, f.y);
        f = *(const float2*)(q0p + kc * 16 + 8); aq[kc][2] = pk2(f.x, f.y);
        f = *(const float2*)(q1p + kc * 16 + 8); aq[kc][3] = pk2(f.x, f.y);
    }
    __syncthreads();

    // ---- S = Q K^T  (26 n-atoms x 2 k-chunks) ----
    float S[26][4];
    #pragma unroll
    for (int na = 0; na < 26; na++)
        #pragma unroll
        for (int e = 0; e < 4; e++) S[na][e] = 0.0f;

    #pragma unroll
    for (int kc = 0; kc < 2; kc++) {
        #pragma unroll
        for (int na = 0; na < 26; na++) {
            const unsigned b0 = Kp[kc * 8 + tg][na * 8 + g];
            const unsigned b1 = Kp[kc * 8 + tg + 4][na * 8 + g];
            mma16(S[na], aq[kc][0], aq[kc][1], aq[kc][2], aq[kc][3], b0, b1);
        }
    }

    // ---- masked softmax (unnormalized) + pack P into A-frag layout ----
    const int r0q0 = min(max(qi0 - 3, 0), H_ - 7) - ki0;
    const int c0q0 = min(max(qj0 - 3, 0), W_ - 7) - kj0;
    const int cb0  = (ki0 - qi0 + 6) * 13 + (kj0 - qj0 + 6);
    const int r0q1 = min(max(qi1 - 3, 0), H_ - 7) - ki0;
    const int c0q1 = min(max(qj1 - 3, 0), W_ - 7) - kj0;
    const int cb1  = (ki0 - qi1 + 6) * 13 + (kj0 - qj1 + 6);

    float sum0 = 0.0f, sum1 = 0.0f;
    unsigned Ph[13][4], Pl[13][4];
    #pragma unroll
    for (int kc = 0; kc < 13; kc++) {
        float p[2][4];
        #pragma unroll
        for (int sub = 0; sub < 2; sub++) {
            const int na = kc * 2 + sub;
            const int c0 = na * 8 + tg * 2;
            const int ra = c0 / 14, ca = c0 - ra * 14;
            const int c1 = c0 + 1;
            const int rb = c1 / 14, cbc = c1 - rb * 14;
            p[sub][0] = pexp(S[na][0], ra, ca,  r0q0, c0q0, cb0, sum0, bs);
            p[sub][1] = pexp(S[na][1], rb, cbc, r0q0, c0q0, cb0, sum0, bs);
            p[sub][2] = pexp(S[na][2], ra, ca,  r0q1, c0q1, cb1, sum1, bs);
            p[sub][3] = pexp(S[na][3], rb, cbc, r0q1, c0q1, cb1, sum1, bs);
        }
        packhl(p[0][0], p[0][1], Ph[kc][0], Pl[kc][0]);
        packhl(p[0][2], p[0][3], Ph[kc][1], Pl[kc][1]);
        packhl(p[1][0], p[1][1], Ph[kc][2], Pl[kc][2]);
        packhl(p[1][2], p[1][3], Ph[kc][3], Pl[kc][3]);
    }
    sum0 += __shfl_xor_sync(0xffffffffu, sum0, 1);
    sum0 += __shfl_xor_sync(0xffffffffu, sum0, 2);
    sum1 += __shfl_xor_sync(0xffffffffu, sum1, 1);
    sum1 += __shfl_xor_sync(0xffffffffu, sum1, 2);
    const float inv0 = 1.0f / sum0;
    const float inv1 = 1.0f / sum1;

    // ---- O = P V  (13 k-chunks x 4 n-atoms, 3-pass) ----
    float o[4][4];
    #pragma unroll
    for (int na = 0; na < 4; na++)
        #pragma unroll
        for (int e = 0; e < 4; e++) o[na][e] = 0.0f;

    #pragma unroll
    for (int kc = 0; kc < 13; kc++) {
        unsigned vh0[4], vh1[4], vl0[4], vl1[4];
        #pragma unroll
        for (int na = 0; na < 4; na++) {
            vh0[na] = Vph[kc * 8 + tg][na * 8 + g];
            vh1[na] = Vph[kc * 8 + tg + 4][na * 8 + g];
            vl0[na] = Vpl[kc * 8 + tg][na * 8 + g];
            vl1[na] = Vpl[kc * 8 + tg + 4][na * 8 + g];
        }
        #pragma unroll
        for (int na = 0; na < 4; na++)
            mma16(o[na], Ph[kc][0], Ph[kc][1], Ph[kc][2], Ph[kc][3], vh0[na], vh1[na]);
        #pragma unroll
        for (int na = 0; na < 4; na++)
            mma16(o[na], Ph[kc][0], Ph[kc][1], Ph[kc][2], Ph[kc][3], vl0[na], vl1[na]);
        #pragma unroll
        for (int na = 0; na < 4; na++)
            mma16(o[na], Pl[kc][0], Pl[kc][1], Pl[kc][2], Pl[kc][3], vh0[na], vh1[na]);
    }

    float* o0p = g_attn + ((size_t)(b * HW_) + qi0 * W_ + qj0) * C_ + h * HD_ + tg * 2;
    float* o1p = g_attn + ((size_t)(b * HW_) + qi1 * W_ + qj1) * C_ + h * HD_ + tg * 2;
    #pragma unroll
    for (int na = 0; na < 4; na++) {
        *(float2*)(o0p + na * 8) = make_float2(o[na][0] * inv0, o[na][1] * inv0);
        *(float2*)(o1p + na * 8) = make_float2(o[na][2] * inv1, o[na][3] * inv1);
    }
}

// ---------------------------------------------------------------------------
extern "C" void kernel_launch(void* const* d_in, const int* in_sizes, int n_in,
                              void* d_out, int out_size)
{
    const float* x      = (const float*)d_in[0];
    const float* w_qkv  = (const float*)d_in[1];
    const float* b_qkv  = (const float*)d_in[2];
    const float* rpb    = (const float*)d_in[3];
    const float* w_proj = (const float*)d_in[4];
    const float* b_proj = (const float*)d_in[5];
    float* out = (float*)d_out;

    gemm_bf<384, true ><<<dim3(98, 3), 512>>>(x, w_qkv, b_qkv, nullptr);
    attn_tc<<<dim3(49, NH_, B_), 128>>>(rpb);
    gemm_bf<128, false><<<dim3(98, 1), 512>>>(nullptr, w_proj, b_proj, out);
}

// round 12
// speedup vs baseline: 1.1874x; 1.1874x over previous
#include <cuda_runtime.h>
#include <cuda_bf16.h>

#define DEVI __device__ __forceinline__

constexpr int B_  = 4;
constexpr int H_  = 56;
constexpr int W_  = 56;
constexpr int C_  = 128;
constexpr int NH_ = 4;
constexpr int HD_ = 32;
constexpr int HW_ = H_ * W_;      // 3136
constexpr int M_  = B_ * HW_;     // 12544
constexpr float LOG2E  = 1.4426950408889634f;
constexpr float QSCALE = 0.17677669529663687f; // 32^-0.5

// ---------------- scratch (device globals; referenced from DEVICE code only) --
__device__ __align__(16) unsigned g_Xh[64 * M_], g_Xl[64 * M_];     // x split, k-major [kp][m]
__device__ __align__(16) unsigned g_Wqh[64 * 384], g_Wql[64 * 384]; // w_qkv split [kp][n]
__device__ __align__(16) unsigned g_Wph[64 * 128], g_Wpl[64 * 128]; // w_proj split [kp][n]
__device__ __align__(16) unsigned g_Q[B_ * NH_ * HW_ * 16];         // [b][h][pix][dp] bf16x2 (scaled)
__device__ __align__(16) unsigned g_K[B_ * NH_ * HW_ * 16];
__device__ __align__(16) unsigned g_Vh[B_ * NH_ * HW_ * 16];
__device__ __align__(16) unsigned g_Vl[B_ * NH_ * HW_ * 16];
__device__ __align__(16) unsigned g_Ah[64 * M_], g_Al[64 * M_];     // attn out split, k-major [kp][m]

// ---------------- helpers ---------------------------------------------------
DEVI unsigned pk2(float x, float y) {            // x->low, y->high
    unsigned u;
    asm("cvt.rn.bf16x2.f32 %0, %1, %2;" : "=r"(u) : "f"(y), "f"(x));
    return u;
}
DEVI void bsplit(float x, float &h, float &l) {
    __nv_bfloat16 b = __float2bfloat16(x);
    h = __bfloat162float(b);
    l = x - h;
}
DEVI unsigned prmtb(unsigned a, unsigned b, unsigned sel) {
    unsigned d;
    asm("prmt.b32 %0, %1, %2, %3;" : "=r"(d) : "r"(a), "r"(b), "r"(sel));
    return d;
}
DEVI void mma16(float* c, unsigned a0, unsigned a1, unsigned a2, unsigned a3,
                unsigned b0, unsigned b1) {
    asm("mma.sync.aligned.m16n8k16.row.col.f32.bf16.bf16.f32 "
        "{%0,%1,%2,%3},{%4,%5,%6,%7},{%8,%9},{%0,%1,%2,%3};"
        : "+f"(c[0]), "+f"(c[1]), "+f"(c[2]), "+f"(c[3])
        : "r"(a0), "r"(a1), "r"(a2), "r"(a3), "r"(b0), "r"(b1));
}
DEVI unsigned su32(const void* p) { return (unsigned)__cvta_generic_to_shared(p); }
DEVI void cpa16(unsigned dst, const void* src) {
    asm volatile("cp.async.cg.shared.global [%0], [%1], 16;" :: "r"(dst), "l"(src));
}
DEVI void cpcommit() { asm volatile("cp.async.commit_group;"); }

// ---------------------------------------------------------------------------
// Prepass: split x / w_qkv / w_proj into hi/lo bf16x2, k-major layout.
// blocks 0..195: x tiles (64 rows).  196: w_qkv.  197: w_proj.
// ---------------------------------------------------------------------------
__global__ void __launch_bounds__(256) prepass(const float* __restrict__ x,
                                               const float* __restrict__ wq,
                                               const float* __restrict__ wp)
{
    const int bx = blockIdx.x, tid = threadIdx.x;
    if (bx < 196) {
        __shared__ float xs[64][129];
        const int m0 = bx * 64;
        #pragma unroll
        for (int i = 0; i < 8; i++) {
            const int f = tid + i * 256;
            const int row = f >> 5, c4 = (f & 31) * 4;
            const float4 v = *(const float4*)(x + (size_t)(m0 + row) * 128 + c4);
            xs[row][c4 + 0] = v.x; xs[row][c4 + 1] = v.y;
            xs[row][c4 + 2] = v.z; xs[row][c4 + 3] = v.w;
        }
        __syncthreads();
        #pragma unroll
        for (int i = 0; i < 16; i++) {
            const int u = tid + i * 256;
            const int m = u & 63, kp = u >> 6;
            float ha, la, hb, lb;
            bsplit(xs[m][2 * kp], ha, la);
            bsplit(xs[m][2 * kp + 1], hb, lb);
            g_Xh[kp * M_ + m0 + m] = pk2(ha, hb);
            g_Xl[kp * M_ + m0 + m] = pk2(la, lb);
        }
    } else if (bx == 196) {
        for (int u = tid; u < 64 * 384; u += 256) {
            const int n = u % 384, kp = u / 384;
            float ha, la, hb, lb;
            bsplit(wq[(2 * kp) * 384 + n], ha, la);
            bsplit(wq[(2 * kp + 1) * 384 + n], hb, lb);
            g_Wqh[u] = pk2(ha, hb);
            g_Wql[u] = pk2(la, lb);
        }
    } else {
        for (int u = tid; u < 64 * 128; u += 256) {
            const int n = u % 128, kp = u / 128;
            float ha, la, hb, lb;
            bsplit(wp[(2 * kp) * 128 + n], ha, la);
            bsplit(wp[(2 * kp + 1) * 128 + n], hb, lb);
            g_Wph[u] = pk2(ha, hb);
            g_Wpl[u] = pk2(la, lb);
        }
    }
}

// ---------------------------------------------------------------------------
// GEMM, operands pre-split in gmem (k-major), selected DEVICE-SIDE by QKV.
// 256 thr = 8 warps (2m x 4n), block tile 128x128, warp tile 64x32, BK=16,
// cp.async 2-stage pipeline. smem row stride 136 (==8 mod 32): conflict-free.
// QKV: writes g_Q (scaled bf16), g_K (bf16), g_Vh/g_Vl. else: fp32 out+bias.
// ---------------------------------------------------------------------------
constexpr int SBUF = 4 * 8 * 136 * 4;   // bytes per stage buffer (17408)

template<int N, bool QKV>
__global__ void __launch_bounds__(256, 2) gemm_pk(const float* __restrict__ bias,
                                                  float* __restrict__ Cout)
{
    __shared__ __align__(16) unsigned Sh[2][4][8][136]; // [buf][Ah,Al,Bh,Bl][kp][col]

    // scratch operands resolved in device code (host cannot pass these symbols)
    const unsigned* __restrict__ AH = QKV ? g_Xh : g_Ah;
    const unsigned* __restrict__ AL = QKV ? g_Xl : g_Al;
    const unsigned* __restrict__ BH = QKV ? g_Wqh : g_Wph;
    const unsigned* __restrict__ BL = QKV ? g_Wql : g_Wpl;

    const int tid  = threadIdx.x;
    const int lane = tid & 31, wid = tid >> 5;
    const int g = lane >> 2, tg = lane & 3;
    const int wm = wid >> 2, wn = wid & 3;
    const int m0 = blockIdx.x * 128, n0 = blockIdx.y * 128;

    // 4 cp.async chunks per thread: chunk j covers array j, row=warp, col=lane*4
    const unsigned* gp[4];
    unsigned sa[4];
    int gstep[4];
    #pragma unroll
    for (int j = 0; j < 4; j++) {
        const int rr  = (tid >> 5) & 7;
        const int off = (tid & 31) * 4;
        sa[j] = su32(&Sh[0][j][rr][off]);
        if (j == 0)      { gp[j] = AH + (size_t)rr * M_ + m0 + off; gstep[j] = 8 * M_; }
        else if (j == 1) { gp[j] = AL + (size_t)rr * M_ + m0 + off; gstep[j] = 8 * M_; }
        else if (j == 2) { gp[j] = BH + (size_t)rr * N  + n0 + off; gstep[j] = 8 * N;  }
        else             { gp[j] = BL + (size_t)rr * N  + n0 + off; gstep[j] = 8 * N;  }
    }

    auto issue = [&](int buf) {
        #pragma unroll
        for (int j = 0; j < 4; j++) {
            cpa16(sa[j] + buf * SBUF, gp[j]);
            gp[j] += gstep[j];
        }
        cpcommit();
    };

    float acc[4][4][4];
    #pragma unroll
    for (int i = 0; i < 4; i++)
        #pragma unroll
        for (int j = 0; j < 4; j++)
            #pragma unroll
            for (int e = 0; e < 4; e++) acc[i][j][e] = 0.0f;

    issue(0);
    issue(1);

    #pragma unroll 1
    for (int s = 0; s < 8; s++) {
        if (s < 7) asm volatile("cp.async.wait_group 1;");
        else       asm volatile("cp.async.wait_group 0;");
        __syncthreads();

        const int buf = s & 1;
        unsigned bh0[4], bh1[4], bl0[4], bl1[4];
        #pragma unroll
        for (int na = 0; na < 4; na++) {
            const int n = wn * 32 + na * 8 + g;
            bh0[na] = Sh[buf][2][tg][n];     bh1[na] = Sh[buf][2][tg + 4][n];
            bl0[na] = Sh[buf][3][tg][n];     bl1[na] = Sh[buf][3][tg + 4][n];
        }
        #pragma unroll
        for (int ma = 0; ma < 4; ma++) {
            const int m = wm * 64 + ma * 16 + g;
            const unsigned ah0 = Sh[buf][0][tg][m],     ah1 = Sh[buf][0][tg][m + 8];
            const unsigned ah2 = Sh[buf][0][tg + 4][m], ah3 = Sh[buf][0][tg + 4][m + 8];
            const unsigned al0 = Sh[buf][1][tg][m],     al1 = Sh[buf][1][tg][m + 8];
            const unsigned al2 = Sh[buf][1][tg + 4][m], al3 = Sh[buf][1][tg + 4][m + 8];
            #pragma unroll
            for (int na = 0; na < 4; na++)
                mma16(acc[ma][na], ah0, ah1, ah2, ah3, bh0[na], bh1[na]);
            #pragma unroll
            for (int na = 0; na < 4; na++)
                mma16(acc[ma][na], ah0, ah1, ah2, ah3, bl0[na], bl1[na]);
            #pragma unroll
            for (int na = 0; na < 4; na++)
                mma16(acc[ma][na], al0, al1, al2, al3, bh0[na], bh1[na]);
        }
        __syncthreads();
        if (s < 6) issue(buf);
    }

    // ---- epilogue ----
    #pragma unroll
    for (int ma = 0; ma < 4; ma++) {
        #pragma unroll
        for (int half = 0; half < 2; half++) {
            const int m = m0 + wm * 64 + ma * 16 + g + half * 8;
            #pragma unroll
            for (int na = 0; na < 4; na++) {
                const int nl = wn * 32 + na * 8 + tg * 2;
                const float2 bv = *(const float2*)&bias[n0 + nl];
                float o0 = acc[ma][na][half * 2 + 0] + bv.x;
                float o1 = acc[ma][na][half * 2 + 1] + bv.y;
                if (QKV) {
                    const int which = n0 >> 7;          // 0=q,1=k,2=v
                    const int bb  = m / HW_;
                    const int pix = m - bb * HW_;
                    const unsigned idx =
                        (unsigned)(((bb * NH_ + wn) * HW_ + pix) * 16 + na * 4 + tg);
                    if (which == 0) {
                        g_Q[idx] = pk2(o0 * (QSCALE * LOG2E), o1 * (QSCALE * LOG2E));
                    } else if (which == 1) {
                        g_K[idx] = pk2(o0, o1);
                    } else {
                        float h0, l0, h1, l1;
                        bsplit(o0, h0, l0); bsplit(o1, h1, l1);
                        g_Vh[idx] = pk2(h0, h1);
                        g_Vl[idx] = pk2(l0, l1);
                    }
                } else {
                    *(float2*)&Cout[(size_t)m * 128 + nl] = make_float2(o0, o1);
                }
            }
        }
    }
}

// ---------------------------------------------------------------------------
// Tensor-core neighborhood attention (bf16 inputs pre-packed in gmem).
// CTA = 128 thr = 8x8 query tile for one (b, head).
// ---------------------------------------------------------------------------
constexpr int KSTR = 232;
constexpr int VSTR = 40;

DEVI float pexp(float s, int r, int cc, int r0q, int c0q, int cb,
                float &sum, const float* bs) {
    const bool v = ((unsigned)(r - r0q) < 7u) && ((unsigned)(cc - c0q) < 7u);
    const int idx = v ? (cb + r * 13 + cc) : 0;
    const float pr = v ? exp2f(s + bs[idx]) : 0.0f;
    sum += pr;
    return pr;
}

__global__ void __launch_bounds__(128) attn_tc(const float* __restrict__ rpb)
{
    __shared__ unsigned Kp[16][KSTR];      // 14848 B
    __shared__ unsigned Vph[104][VSTR];    // 16640 B
    __shared__ unsigned Vpl[104][VSTR];    // 16640 B
    __shared__ float bs[169];              //   676 B

    const int b  = blockIdx.z;
    const int h  = blockIdx.y;
    const int i0 = (blockIdx.x / 7) * 8;
    const int j0 = (blockIdx.x % 7) * 8;
    const int ki0 = min(max(i0 - 3, 0), H_ - 7);
    const int kj0 = min(max(j0 - 3, 0), W_ - 7);
    const int tid = threadIdx.x, lane = tid & 31, w = tid >> 5;
    const int g = lane >> 2, tg = lane & 3;

    const size_t hb = (size_t)(b * NH_ + h) * HW_ * 16;
    const unsigned* qbp = g_Q + hb;
    const unsigned* kbp = g_K + hb;
    const unsigned* vhp = g_Vh + hb;
    const unsigned* vlp = g_Vl + hb;

    for (int x = tid; x < 169; x += 128) bs[x] = rpb[h * 169 + x] * LOG2E;

    // ---- K tile: direct packed load ----
    for (int key = tid; key < 208; key += 128) {
        if (key < 196) {
            const int gi = ki0 + key / 14, gj = kj0 + key % 14;
            const uint4* p = (const uint4*)(kbp + (size_t)(gi * W_ + gj) * 16);
            #pragma unroll
            for (int t = 0; t < 4; t++) {
                const uint4 u = p[t];
                Kp[4 * t + 0][key] = u.x;
                Kp[4 * t + 1][key] = u.y;
                Kp[4 * t + 2][key] = u.z;
                Kp[4 * t + 3][key] = u.w;
            }
        } else {
            #pragma unroll
            for (int dp = 0; dp < 16; dp++) Kp[dp][key] = 0u;
        }
    }

    // ---- V tile: key-pair transpose via PRMT ----
    #pragma unroll 1
    for (int it = 0; it < 13; it++) {
        const int idx = it * 128 + tid;      // 0..1663 = 104 kp x 16 dp
        const int e  = idx & 15;
        const int kp = idx >> 4;
        const int k0 = 2 * kp, k1 = 2 * kp + 1;
        unsigned u0h = 0u, u1h = 0u, u0l = 0u, u1l = 0u;
        if (k0 < 196) {
            const int gi = ki0 + k0 / 14, gj = kj0 + k0 % 14;
            const size_t o = (size_t)(gi * W_ + gj) * 16 + e;
            u0h = vhp[o]; u0l = vlp[o];
        }
        if (k1 < 196) {
            const int gi = ki0 + k1 / 14, gj = kj0 + k1 % 14;
            const size_t o = (size_t)(gi * W_ + gj) * 16 + e;
            u1h = vhp[o]; u1l = vlp[o];
        }
        *(uint2*)&Vph[kp][2 * e] = make_uint2(prmtb(u0h, u1h, 0x5410u),
                                              prmtb(u0h, u1h, 0x7632u));
        *(uint2*)&Vpl[kp][2 * e] = make_uint2(prmtb(u0l, u1l, 0x5410u),
                                              prmtb(u0l, u1l, 0x7632u));
    }

    // ---- Q fragments: direct packed loads ----
    const int ql0 = w * 16 + g, ql1 = ql0 + 8;
    const int qi0 = i0 + (ql0 >> 3), qj0 = j0 + (ql0 & 7);
    const int qi1 = i0 + (ql1 >> 3), qj1 = j0 + (ql1 & 7);
    const int qpix0 = qi0 * W_ + qj0;
    const int qpix1 = qi1 * W_ + qj1;
    unsigned aq[2][4];
    #pragma unroll
    for (int kc = 0; kc < 2; kc++) {
        aq[kc][0] = qbp[(size_t)qpix0 * 16 + kc * 8 + tg];
        aq[kc][1] = qbp[(size_t)qpix1 * 16 + kc * 8 + tg];
        aq[kc][2] = qbp[(size_t)qpix0 * 16 + kc * 8 + tg + 4];
        aq[kc][3] = qbp[(size_t)qpix1 * 16 + kc * 8 + tg + 4];
    }
    __syncthreads();

    // ---- S = Q K^T ----
    float S[26][4];
    #pragma unroll
    for (int na = 0; na < 26; na++)
        #pragma unroll
        for (int e = 0; e < 4; e++) S[na][e] = 0.0f;

    #pragma unroll
    for (int kc = 0; kc < 2; kc++) {
        #pragma unroll
        for (int na = 0; na < 26; na++) {
            const unsigned b0 = Kp[kc * 8 + tg][na * 8 + g];
            const unsigned b1 = Kp[kc * 8 + tg + 4][na * 8 + g];
            mma16(S[na], aq[kc][0], aq[kc][1], aq[kc][2], aq[kc][3], b0, b1);
        }
    }

    // ---- masked softmax + pack P (A-frag layout) ----
    const int r0q0 = min(max(qi0 - 3, 0), H_ - 7) - ki0;
    const int c0q0 = min(max(qj0 - 3, 0), W_ - 7) - kj0;
    const int cb0  = (ki0 - qi0 + 6) * 13 + (kj0 - qj0 + 6);
    const int r0q1 = min(max(qi1 - 3, 0), H_ - 7) - ki0;
    const int c0q1 = min(max(qj1 - 3, 0), W_ - 7) - kj0;
    const int cb1  = (ki0 - qi1 + 6) * 13 + (kj0 - qj1 + 6);

    float sum0 = 0.0f, sum1 = 0.0f;
    unsigned Ph[13][4], Pl[13][4];
    #pragma unroll
    for (int kc = 0; kc < 13; kc++) {
        float p[2][4];
        #pragma unroll
        for (int sub = 0; sub < 2; sub++) {
            const int na = kc * 2 + sub;
            const int c0 = na * 8 + tg * 2;
            const int ra = c0 / 14, ca = c0 - ra * 14;
            const int c1 = c0 + 1;
            const int rb = c1 / 14, cbc = c1 - rb * 14;
            p[sub][0] = pexp(S[na][0], ra, ca,  r0q0, c0q0, cb0, sum0, bs);
            p[sub][1] = pexp(S[na][1], rb, cbc, r0q0, c0q0, cb0, sum0, bs);
            p[sub][2] = pexp(S[na][2], ra, ca,  r0q1, c0q1, cb1, sum1, bs);
            p[sub][3] = pexp(S[na][3], rb, cbc, r0q1, c0q1, cb1, sum1, bs);
        }
        float h0, l0, h1, l1;
        bsplit(p[0][0], h0, l0); bsplit(p[0][1], h1, l1);
        Ph[kc][0] = pk2(h0, h1); Pl[kc][0] = pk2(l0, l1);
        bsplit(p[0][2], h0, l0); bsplit(p[0][3], h1, l1);
        Ph[kc][1] = pk2(h0, h1); Pl[kc][1] = pk2(l0, l1);
        bsplit(p[1][0], h0, l0); bsplit(p[1][1], h1, l1);
        Ph[kc][2] = pk2(h0, h1); Pl[kc][2] = pk2(l0, l1);
        bsplit(p[1][2], h0, l0); bsplit(p[1][3], h1, l1);
        Ph[kc][3] = pk2(h0, h1); Pl[kc][3] = pk2(l0, l1);
    }
    sum0 += __shfl_xor_sync(0xffffffffu, sum0, 1);
    sum0 += __shfl_xor_sync(0xffffffffu, sum0, 2);
    sum1 += __shfl_xor_sync(0xffffffffu, sum1, 1);
    sum1 += __shfl_xor_sync(0xffffffffu, sum1, 2);
    const float inv0 = 1.0f / sum0;
    const float inv1 = 1.0f / sum1;

    // ---- O = P V (3-pass) ----
    float o[4][4];
    #pragma unroll
    for (int na = 0; na < 4; na++)
        #pragma unroll
        for (int e = 0; e < 4; e++) o[na][e] = 0.0f;

    #pragma unroll
    for (int kc = 0; kc < 13; kc++) {
        unsigned vh0[4], vh1[4], vl0[4], vl1[4];
        #pragma unroll
        for (int na = 0; na < 4; na++) {
            vh0[na] = Vph[kc * 8 + tg][na * 8 + g];
            vh1[na] = Vph[kc * 8 + tg + 4][na * 8 + g];
            vl0[na] = Vpl[kc * 8 + tg][na * 8 + g];
            vl1[na] = Vpl[kc * 8 + tg + 4][na * 8 + g];
        }
        #pragma unroll
        for (int na = 0; na < 4; na++)
            mma16(o[na], Ph[kc][0], Ph[kc][1], Ph[kc][2], Ph[kc][3], vh0[na], vh1[na]);
        #pragma unroll
        for (int na = 0; na < 4; na++)
            mma16(o[na], Ph[kc][0], Ph[kc][1], Ph[kc][2], Ph[kc][3], vl0[na], vl1[na]);
        #pragma unroll
        for (int na = 0; na < 4; na++)
            mma16(o[na], Pl[kc][0], Pl[kc][1], Pl[kc][2], Pl[kc][3], vh0[na], vh1[na]);
    }

    // ---- write attn output pre-split, k-major [kp][m] for proj GEMM ----
    const int mm0 = b * HW_ + qpix0;
    const int mm1 = b * HW_ + qpix1;
    #pragma unroll
    for (int na = 0; na < 4; na++) {
        const int kp = h * 16 + na * 4 + tg;
        float h0, l0, h1, l1;
        bsplit(o[na][0] * inv0, h0, l0); bsplit(o[na][1] * inv0, h1, l1);
        g_Ah[kp * M_ + mm0] = pk2(h0, h1);
        g_Al[kp * M_ + mm0] = pk2(l0, l1);
        bsplit(o[na][2] * inv1, h0, l0); bsplit(o[na][3] * inv1, h1, l1);
        g_Ah[kp * M_ + mm1] = pk2(h0, h1);
        g_Al[kp * M_ + mm1] = pk2(l0, l1);
    }
}

// ---------------------------------------------------------------------------
extern "C" void kernel_launch(void* const* d_in, const int* in_sizes, int n_in,
                              void* d_out, int out_size)
{
    const float* x      = (const float*)d_in[0];
    const float* w_qkv  = (const float*)d_in[1];
    const float* b_qkv  = (const float*)d_in[2];
    const float* rpb    = (const float*)d_in[3];
    const float* w_proj = (const float*)d_in[4];
    const float* b_proj = (const float*)d_in[5];
    float* out = (float*)d_out;

    prepass<<<198, 256>>>(x, w_qkv, w_proj);
    gemm_pk<384, true ><<<dim3(98, 3), 256>>>(b_qkv, nullptr);
    attn_tc<<<dim3(49, NH_, B_), 128>>>(rpb);
    gemm_pk<128, false><<<dim3(98, 1), 256>>>(b_proj, out);
}

// round 16
// speedup vs baseline: 1.2431x; 1.0469x over previous
#include <cuda_runtime.h>
#include <cuda_bf16.h>

#define DEVI __device__ __forceinline__

constexpr int B_  = 4;
constexpr int H_  = 56;
constexpr int W_  = 56;
constexpr int C_  = 128;
constexpr int NH_ = 4;
constexpr int HD_ = 32;
constexpr int HW_ = H_ * W_;      // 3136
constexpr int M_  = B_ * HW_;     // 12544
constexpr float LOG2E  = 1.4426950408889634f;
constexpr float QSCALE = 0.17677669529663687f; // 32^-0.5

// ---------------- scratch (device globals; referenced from DEVICE code only) --
__device__ __align__(16) unsigned g_Xh[64 * M_], g_Xl[64 * M_];     // x split, k-major [kp][m]
__device__ __align__(16) unsigned g_Wqh[64 * 384], g_Wql[64 * 384]; // w_qkv split [kp][n]
__device__ __align__(16) unsigned g_Wph[64 * 128], g_Wpl[64 * 128]; // w_proj split [kp][n]
__device__ __align__(16) unsigned g_Q[B_ * NH_ * HW_ * 16];         // [b][h][pix][dp] bf16x2 (scaled)
__device__ __align__(16) unsigned g_K[B_ * NH_ * HW_ * 16];
__device__ __align__(16) unsigned g_Vh[B_ * NH_ * HW_ * 16];
__device__ __align__(16) unsigned g_Vl[B_ * NH_ * HW_ * 16];
__device__ __align__(16) unsigned g_Ah[64 * M_], g_Al[64 * M_];     // attn out split, k-major [kp][m]

// ---------------- helpers ---------------------------------------------------
DEVI unsigned pk2(float x, float y) {            // x->low, y->high
    unsigned u;
    asm("cvt.rn.bf16x2.f32 %0, %1, %2;" : "=r"(u) : "f"(y), "f"(x));
    return u;
}
DEVI void bsplit(float x, float &h, float &l) {
    __nv_bfloat16 b = __float2bfloat16(x);
    h = __bfloat162float(b);
    l = x - h;
}
DEVI unsigned prmtb(unsigned a, unsigned b, unsigned sel) {
    unsigned d;
    asm("prmt.b32 %0, %1, %2, %3;" : "=r"(d) : "r"(a), "r"(b), "r"(sel));
    return d;
}
DEVI void mma16(float* c, unsigned a0, unsigned a1, unsigned a2, unsigned a3,
                unsigned b0, unsigned b1) {
    asm("mma.sync.aligned.m16n8k16.row.col.f32.bf16.bf16.f32 "
        "{%0,%1,%2,%3},{%4,%5,%6,%7},{%8,%9},{%0,%1,%2,%3};"
        : "+f"(c[0]), "+f"(c[1]), "+f"(c[2]), "+f"(c[3])
        : "r"(a0), "r"(a1), "r"(a2), "r"(a3), "r"(b0), "r"(b1));
}
DEVI unsigned su32(const void* p) { return (unsigned)__cvta_generic_to_shared(p); }
DEVI void cpa16(unsigned dst, const void* src) {
    asm volatile("cp.async.cg.shared.global [%0], [%1], 16;" :: "r"(dst), "l"(src));
}
DEVI void cpcommit() { asm volatile("cp.async.commit_group;"); }

// ---------------------------------------------------------------------------
// Prepass: split x / w_qkv / w_proj into hi/lo bf16x2, k-major layout.
// ---------------------------------------------------------------------------
__global__ void __launch_bounds__(256) prepass(const float* __restrict__ x,
                                               const float* __restrict__ wq,
                                               const float* __restrict__ wp)
{
    const int bx = blockIdx.x, tid = threadIdx.x;
    if (bx < 196) {
        __shared__ float xs[64][129];
        const int m0 = bx * 64;
        #pragma unroll
        for (int i = 0; i < 8; i++) {
            const int f = tid + i * 256;
            const int row = f >> 5, c4 = (f & 31) * 4;
            const float4 v = *(const float4*)(x + (size_t)(m0 + row) * 128 + c4);
            xs[row][c4 + 0] = v.x; xs[row][c4 + 1] = v.y;
            xs[row][c4 + 2] = v.z; xs[row][c4 + 3] = v.w;
        }
        __syncthreads();
        #pragma unroll
        for (int i = 0; i < 16; i++) {
            const int u = tid + i * 256;
            const int m = u & 63, kp = u >> 6;
            float ha, la, hb, lb;
            bsplit(xs[m][2 * kp], ha, la);
            bsplit(xs[m][2 * kp + 1], hb, lb);
            g_Xh[kp * M_ + m0 + m] = pk2(ha, hb);
            g_Xl[kp * M_ + m0 + m] = pk2(la, lb);
        }
    } else if (bx == 196) {
        for (int u = tid; u < 64 * 384; u += 256) {
            const int n = u % 384, kp = u / 384;
            float ha, la, hb, lb;
            bsplit(wq[(2 * kp) * 384 + n], ha, la);
            bsplit(wq[(2 * kp + 1) * 384 + n], hb, lb);
            g_Wqh[u] = pk2(ha, hb);
            g_Wql[u] = pk2(la, lb);
        }
    } else {
        for (int u = tid; u < 64 * 128; u += 256) {
            const int n = u % 128, kp = u / 128;
            float ha, la, hb, lb;
            bsplit(wp[(2 * kp) * 128 + n], ha, la);
            bsplit(wp[(2 * kp + 1) * 128 + n], hb, lb);
            g_Wph[u] = pk2(ha, hb);
            g_Wpl[u] = pk2(la, lb);
        }
    }
}

// ---------------------------------------------------------------------------
// GEMM: block tile 64x128, BK=16, 3-stage cp.async, ONE sync per stage.
// 256 thr = 8 warps (2m x 4n), warp tile 32x32.
// Stage layout (uints): Ah[8][72] @0, Al @576, Bh[8][136] @1152, Bl @2240.
// Strides 72/136 == 8 mod 32 -> all fragment LDS conflict-free.
// ---------------------------------------------------------------------------
constexpr int STGU = 3328;               // uints per stage

template<int N, bool QKV>
__global__ void __launch_bounds__(256, 3) gemm_pk(const float* __restrict__ bias,
                                                  float* __restrict__ Cout)
{
    __shared__ __align__(16) unsigned S3[3][STGU];   // 39936 B

    const unsigned* __restrict__ AH = QKV ? g_Xh : g_Ah;
    const unsigned* __restrict__ AL = QKV ? g_Xl : g_Al;
    const unsigned* __restrict__ BH = QKV ? g_Wqh : g_Wph;
    const unsigned* __restrict__ BL = QKV ? g_Wql : g_Wpl;

    const int tid  = threadIdx.x;
    const int lane = tid & 31, wid = tid >> 5;
    const int g = lane >> 2, tg = lane & 3;
    const int wm = wid >> 2, wn = wid & 3;
    const int m0 = blockIdx.x * 64, n0 = blockIdx.y * 128;

    // A: 1 chunk/thread (2 arrays x 8 rows x 16 col4), B: 2 chunks/thread
    const int a_arr = tid >> 7, a_row = (tid >> 4) & 7, a_c4 = (tid & 15) * 4;
    const unsigned* gpa = (a_arr ? AL : AH) + (size_t)a_row * M_ + m0 + a_c4;
    const unsigned  saa = su32(&S3[0][a_arr * 576 + a_row * 72 + a_c4]);

    const unsigned* gpb[2];
    unsigned sab[2];
    #pragma unroll
    for (int j = 0; j < 2; j++) {
        const int idx = tid * 2 + j;
        const int b_arr = idx >> 8, b_row = (idx >> 5) & 7, b_c4 = (idx & 31) * 4;
        gpb[j] = (b_arr ? BL : BH) + (size_t)b_row * N + n0 + b_c4;
        sab[j] = su32(&S3[0][1152 + b_arr * 1088 + b_row * 136 + b_c4]);
    }

    auto issue = [&](int stage) {
        const unsigned boff = (unsigned)(stage % 3) * (STGU * 4u);
        cpa16(saa + boff, gpa + (size_t)stage * 8 * M_);
        cpa16(sab[0] + boff, gpb[0] + (size_t)stage * 8 * N);
        cpa16(sab[1] + boff, gpb[1] + (size_t)stage * 8 * N);
        cpcommit();
    };

    float acc[2][4][4];
    #pragma unroll
    for (int i = 0; i < 2; i++)
        #pragma unroll
        for (int j = 0; j < 4; j++)
            #pragma unroll
            for (int e = 0; e < 4; e++) acc[i][j][e] = 0.0f;

    issue(0);
    issue(1);

    #pragma unroll 1
    for (int s = 0; s < 8; s++) {
        if (s == 7) asm volatile("cp.async.wait_group 0;");
        else        asm volatile("cp.async.wait_group 1;");
        __syncthreads();
        if (s + 2 < 8) issue(s + 2);     // into buf (s+2)%3: freed by compute(s-1), fenced by sync

        const unsigned* sb = S3[s % 3];
        unsigned bh0[4], bh1[4], bl0[4], bl1[4];
        #pragma unroll
        for (int na = 0; na < 4; na++) {
            const int n = wn * 32 + na * 8 + g;
            bh0[na] = sb[1152 + tg * 136 + n];        bh1[na] = sb[1152 + (tg + 4) * 136 + n];
            bl0[na] = sb[2240 + tg * 136 + n];        bl1[na] = sb[2240 + (tg + 4) * 136 + n];
        }
        #pragma unroll
        for (int ma = 0; ma < 2; ma++) {
            const int m = wm * 32 + ma * 16 + g;
            const unsigned ah0 = sb[tg * 72 + m],           ah1 = sb[tg * 72 + m + 8];
            const unsigned ah2 = sb[(tg + 4) * 72 + m],     ah3 = sb[(tg + 4) * 72 + m + 8];
            const unsigned al0 = sb[576 + tg * 72 + m],     al1 = sb[576 + tg * 72 + m + 8];
            const unsigned al2 = sb[576 + (tg + 4) * 72 + m], al3 = sb[576 + (tg + 4) * 72 + m + 8];
            #pragma unroll
            for (int na = 0; na < 4; na++)
                mma16(acc[ma][na], ah0, ah1, ah2, ah3, bh0[na], bh1[na]);
            #pragma unroll
            for (int na = 0; na < 4; na++)
                mma16(acc[ma][na], ah0, ah1, ah2, ah3, bl0[na], bl1[na]);
            #pragma unroll
            for (int na = 0; na < 4; na++)
                mma16(acc[ma][na], al0, al1, al2, al3, bh0[na], bh1[na]);
        }
    }

    // ---- epilogue ----
    #pragma unroll
    for (int ma = 0; ma < 2; ma++) {
        #pragma unroll
        for (int half = 0; half < 2; half++) {
            const int m = m0 + wm * 32 + ma * 16 + g + half * 8;
            #pragma unroll
            for (int na = 0; na < 4; na++) {
                const int nl = wn * 32 + na * 8 + tg * 2;
                const float2 bv = *(const float2*)&bias[n0 + nl];
                float o0 = acc[ma][na][half * 2 + 0] + bv.x;
                float o1 = acc[ma][na][half * 2 + 1] + bv.y;
                if (QKV) {
                    const int which = n0 >> 7;          // 0=q,1=k,2=v
                    const int bb  = m / HW_;
                    const int pix = m - bb * HW_;
                    const unsigned idx =
                        (unsigned)(((bb * NH_ + wn) * HW_ + pix) * 16 + na * 4 + tg);
                    if (which == 0) {
                        g_Q[idx] = pk2(o0 * (QSCALE * LOG2E), o1 * (QSCALE * LOG2E));
                    } else if (which == 1) {
                        g_K[idx] = pk2(o0, o1);
                    } else {
                        float h0, l0, h1, l1;
                        bsplit(o0, h0, l0); bsplit(o1, h1, l1);
                        g_Vh[idx] = pk2(h0, h1);
                        g_Vl[idx] = pk2(l0, l1);
                    }
                } else {
                    *(float2*)&Cout[(size_t)m * 128 + nl] = make_float2(o0, o1);
                }
            }
        }
    }
}

// ---------------------------------------------------------------------------
// Tensor-core neighborhood attention, per-warp ROW-WINDOW restriction.
// CTA = 128 thr = 8x8 query tile for one (b,head). Warp w owns query rows
// 2w, 2w+1 whose row windows union to <= 8 rows of the 14-row key union
// starting at rb = clamp-start(row 2w) - ki0. S = Q K^T over 8x14 = 112
// padded cols (was 208): S-MMAs 28, PV-MMAs 84, exp sites 56 per thread.
// K tile shared: per-warp column offset rb*14 (bank pattern preserved).
// ---------------------------------------------------------------------------
__global__ void __launch_bounds__(128) attn_tc(const float* __restrict__ rpb)
{
    __shared__ unsigned Kp[16][200];       // 12800 B
    __shared__ unsigned Vph[98][40];       // 15680 B
    __shared__ unsigned Vpl[98][40];       // 15680 B
    __shared__ float bs[169];              //   676 B   (total 44836)

    const int b  = blockIdx.z;
    const int h  = blockIdx.y;
    const int i0 = (blockIdx.x / 7) * 8;
    const int j0 = (blockIdx.x % 7) * 8;
    const int ki0 = min(max(i0 - 3, 0), H_ - 7);
    const int kj0 = min(max(j0 - 3, 0), W_ - 7);
    const int tid = threadIdx.x, lane = tid & 31, w = tid >> 5;
    const int g = lane >> 2, tg = lane & 3;

    const size_t hb = (size_t)(b * NH_ + h) * HW_ * 16;
    const unsigned* qbp = g_Q + hb;
    const unsigned* kbp = g_K + hb;
    const unsigned* vhp = g_Vh + hb;
    const unsigned* vlp = g_Vl + hb;

    for (int x = tid; x < 169; x += 128) bs[x] = rpb[h * 169 + x] * LOG2E;

    // ---- K tile: 196 union keys, coords clamped (invalid masked later) ----
    for (int key = tid; key < 196; key += 128) {
        const int gi = min(ki0 + key / 14, H_ - 1);
        const int gj = min(kj0 + key % 14, W_ - 1);
        const uint4* p = (const uint4*)(kbp + (size_t)(gi * W_ + gj) * 16);
        #pragma unroll
        for (int t = 0; t < 4; t++) {
            const uint4 u = p[t];
            Kp[4 * t + 0][key] = u.x;
            Kp[4 * t + 1][key] = u.y;
            Kp[4 * t + 2][key] = u.z;
            Kp[4 * t + 3][key] = u.w;
        }
    }

    // ---- V tile: 98 key-pairs x 16 dp, key-pair transpose via PRMT ----
    #pragma unroll 1
    for (int it = 0; it < 13; it++) {
        const int idx = it * 128 + tid;
        if (idx < 1568) {
            const int e  = idx & 15;
            const int kp = idx >> 4;
            const int k0 = 2 * kp, k1 = k0 + 1;
            const int gi0 = min(ki0 + k0 / 14, H_ - 1), gj0 = min(kj0 + k0 % 14, W_ - 1);
            const int gi1 = min(ki0 + k1 / 14, H_ - 1), gj1 = min(kj0 + k1 % 14, W_ - 1);
            const size_t o0 = (size_t)(gi0 * W_ + gj0) * 16 + e;
            const size_t o1 = (size_t)(gi1 * W_ + gj1) * 16 + e;
            const unsigned u0h = vhp[o0], u1h = vhp[o1];
            const unsigned u0l = vlp[o0], u1l = vlp[o1];
            *(uint2*)&Vph[kp][2 * e] = make_uint2(prmtb(u0h, u1h, 0x5410u),
                                                  prmtb(u0h, u1h, 0x7632u));
            *(uint2*)&Vpl[kp][2 * e] = make_uint2(prmtb(u0l, u1l, 0x5410u),
                                                  prmtb(u0l, u1l, 0x7632u));
        }
    }

    // ---- Q fragments ----
    const int qi0 = i0 + 2 * w, qi1 = qi0 + 1;
    const int qj  = j0 + g;
    const int qpix0 = qi0 * W_ + qj;
    const int qpix1 = qi1 * W_ + qj;
    unsigned aq[2][4];
    #pragma unroll
    for (int kc = 0; kc < 2; kc++) {
        aq[kc][0] = qbp[(size_t)qpix0 * 16 + kc * 8 + tg];
        aq[kc][1] = qbp[(size_t)qpix1 * 16 + kc * 8 + tg];
        aq[kc][2] = qbp[(size_t)qpix0 * 16 + kc * 8 + tg + 4];
        aq[kc][3] = qbp[(size_t)qpix1 * 16 + kc * 8 + tg + 4];
    }
    __syncthreads();

    // ---- per-warp row window ----
    const int siA = min(max(qi0 - 3, 0), H_ - 7);
    const int siB = min(max(qi1 - 3, 0), H_ - 7);
    const int rb  = siA - ki0;           // 0..6
    const int d1  = siB - siA;           // 0 or 1
    const int rb14 = rb * 14;

    // ---- S = Q K^T over 112 padded cols (14 n-atoms) ----
    float S[14][4];
    #pragma unroll
    for (int na = 0; na < 14; na++)
        #pragma unroll
        for (int e = 0; e < 4; e++) S[na][e] = 0.0f;

    #pragma unroll
    for (int kc = 0; kc < 2; kc++) {
        #pragma unroll
        for (int na = 0; na < 14; na++) {
            const unsigned b0 = Kp[kc * 8 + tg][rb14 + na * 8 + g];
            const unsigned b1 = Kp[kc * 8 + tg + 4][rb14 + na * 8 + g];
            mma16(S[na], aq[kc][0], aq[kc][1], aq[kc][2], aq[kc][3], b0, b1);
        }
    }

    // ---- masked softmax + pack P (A-frag layout) ----
    const int c0q = min(max(qj - 3, 0), W_ - 7) - kj0;           // shared by both queries
    const int cbA = (ki0 + rb - qi0 + 6) * 13 + (kj0 - qj + 6);
    const int cbB = (ki0 + rb - qi1 + 6) * 13 + (kj0 - qj + 6);

    float sum0 = 0.0f, sum1 = 0.0f;
    unsigned Ph[7][4], Pl[7][4];
    #pragma unroll
    for (int kc = 0; kc < 7; kc++) {
        float p[2][4];
        #pragma unroll
        for (int sub = 0; sub < 2; sub++) {
            const int na = 2 * kc + sub;
            #pragma unroll
            for (int e = 0; e < 2; e++) {
                const int c  = na * 8 + tg * 2 + e;   // local slot 0..111
                const int r  = c / 14;                 // local row 0..7
                const int cc = c - r * 14;             // union col 0..13
                const int t  = r * 13 + cc;
                const bool okc = ((unsigned)(cc - c0q) < 7u);
                const bool okA = (r < 7) && okc;
                const bool okB = ((unsigned)(r - d1) < 7u) && okc;
                const float bA = bs[okA ? (cbA + t) : 0];
                const float bB = bs[okB ? (cbB + t) : 0];
                const float pA = okA ? exp2f(S[na][e] + bA) : 0.0f;
                const float pB = okB ? exp2f(S[na][2 + e] + bB) : 0.0f;
                sum0 += pA; sum1 += pB;
                p[sub][e] = pA; p[sub][2 + e] = pB;
            }
        }
        float h0, l0, h1, l1;
        bsplit(p[0][0], h0, l0); bsplit(p[0][1], h1, l1);
        Ph[kc][0] = pk2(h0, h1); Pl[kc][0] = pk2(l0, l1);
        bsplit(p[0][2], h0, l0); bsplit(p[0][3], h1, l1);
        Ph[kc][1] = pk2(h0, h1); Pl[kc][1] = pk2(l0, l1);
        bsplit(p[1][0], h0, l0); bsplit(p[1][1], h1, l1);
        Ph[kc][2] = pk2(h0, h1); Pl[kc][2] = pk2(l0, l1);
        bsplit(p[1][2], h0, l0); bsplit(p[1][3], h1, l1);
        Ph[kc][3] = pk2(h0, h1); Pl[kc][3] = pk2(l0, l1);
    }
    sum0 += __shfl_xor_sync(0xffffffffu, sum0, 1);
    sum0 += __shfl_xor_sync(0xffffffffu, sum0, 2);
    sum1 += __shfl_xor_sync(0xffffffffu, sum1, 1);
    sum1 += __shfl_xor_sync(0xffffffffu, sum1, 2);
    const float inv0 = 1.0f / sum0;
    const float inv1 = 1.0f / sum1;

    // ---- O = P V over the warp's 112 keys (7 k-chunks, 3-pass) ----
    const int kp0 = rb * 7;
    float o[4][4];
    #pragma unroll
    for (int na = 0; na < 4; na++)
        #pragma unroll
        for (int e = 0; e < 4; e++) o[na][e] = 0.0f;

    #pragma unroll
    for (int kc = 0; kc < 7; kc++) {
        unsigned vh0[4], vh1[4], vl0[4], vl1[4];
        #pragma unroll
        for (int na = 0; na < 4; na++) {
            vh0[na] = Vph[kp0 + kc * 8 + tg][na * 8 + g];
            vh1[na] = Vph[kp0 + kc * 8 + tg + 4][na * 8 + g];
            vl0[na] = Vpl[kp0 + kc * 8 + tg][na * 8 + g];
            vl1[na] = Vpl[kp0 + kc * 8 + tg + 4][na * 8 + g];
        }
        #pragma unroll
        for (int na = 0; na < 4; na++)
            mma16(o[na], Ph[kc][0], Ph[kc][1], Ph[kc][2], Ph[kc][3], vh0[na], vh1[na]);
        #pragma unroll
        for (int na = 0; na < 4; na++)
            mma16(o[na], Ph[kc][0], Ph[kc][1], Ph[kc][2], Ph[kc][3], vl0[na], vl1[na]);
        #pragma unroll
        for (int na = 0; na < 4; na++)
            mma16(o[na], Pl[kc][0], Pl[kc][1], Pl[kc][2], Pl[kc][3], vh0[na], vh1[na]);
    }

    // ---- write attn output pre-split, k-major [kp][m] for proj GEMM ----
    const int mm0 = b * HW_ + qpix0;
    const int mm1 = b * HW_ + qpix1;
    #pragma unroll
    for (int na = 0; na < 4; na++) {
        const int kp = h * 16 + na * 4 + tg;
        float h0, l0, h1, l1;
        bsplit(o[na][0] * inv0, h0, l0); bsplit(o[na][1] * inv0, h1, l1);
        g_Ah[kp * M_ + mm0] = pk2(h0, h1);
        g_Al[kp * M_ + mm0] = pk2(l0, l1);
        bsplit(o[na][2] * inv1, h0, l0); bsplit(o[na][3] * inv1, h1, l1);
        g_Ah[kp * M_ + mm1] = pk2(h0, h1);
        g_Al[kp * M_ + mm1] = pk2(l0, l1);
    }
}

// ---------------------------------------------------------------------------
extern "C" void kernel_launch(void* const* d_in, const int* in_sizes, int n_in,
                              void* d_out, int out_size)
{
    const float* x      = (const float*)d_in[0];
    const float* w_qkv  = (const float*)d_in[1];
    const float* b_qkv  = (const float*)d_in[2];
    const float* rpb    = (const float*)d_in[3];
    const float* w_proj = (const float*)d_in[4];
    const float* b_proj = (const float*)d_in[5];
    float* out = (float*)d_out;

    prepass<<<198, 256>>>(x, w_qkv, w_proj);
    gemm_pk<384, true ><<<dim3(196, 3), 256>>>(b_qkv, nullptr);
    attn_tc<<<dim3(49, NH_, B_), 128>>>(rpb);
    gemm_pk<128, false><<<dim3(196, 1), 256>>>(b_proj, out);
}